// round 4
// baseline (speedup 1.0000x reference)
#include <cuda_runtime.h>
#include <cuda_bf16.h>
#include <cstdint>

// ============================================================================
// Problem: content[64,256], motion[64,512,128] -> M=32768 tokens
//   L1: [M,384]x[384,256]+b1, leaky(0.2)
//   L2: [M,256]x[256,512]+b2, leaky(0.2)
//   L3: [M,512]x[512,1152]+b3 -> out fp32
// Strategy: bf16x3 emulated-fp32 GEMM on mma.sync.m16n8k16.
//   C = Ahi*Bhi + Alo*Bhi + Ahi*Blo (A2B2 dropped, ~4e-6 rel).
//   R4: hi/lo-coalesced K-chunks (load 4 tiles once, run 3 passes) + ldmatrix.
// ============================================================================

__device__ __nv_bfloat16 g_a1hi[12582912];   // [32768,384]
__device__ __nv_bfloat16 g_a1lo[12582912];
__device__ __nv_bfloat16 g_h1hi[8388608];    // [32768,256]
__device__ __nv_bfloat16 g_h1lo[8388608];
__device__ __nv_bfloat16 g_h2hi[16777216];   // [32768,512]
__device__ __nv_bfloat16 g_h2lo[16777216];
__device__ __nv_bfloat16 g_w1hi[98304],  g_w1lo[98304];    // [256,384]  (N,K)
__device__ __nv_bfloat16 g_w2hi[131072], g_w2lo[131072];   // [512,256]
__device__ __nv_bfloat16 g_w3hi[589824], g_w3lo[589824];   // [1152,512]

// ---- helpers ----
__device__ __forceinline__ uint32_t smem_u32(const void* p) {
    uint32_t a;
    asm("{ .reg .u64 t; cvta.to.shared.u64 t, %1; cvt.u32.u64 %0, t; }"
        : "=r"(a) : "l"(p));
    return a;
}
__device__ __forceinline__ void cp16(uint32_t dst, const void* src) {
    asm volatile("cp.async.cg.shared.global [%0], [%1], 16;"
                 :: "r"(dst), "l"(src) : "memory");
}
#define CP_COMMIT() asm volatile("cp.async.commit_group;" ::: "memory")
#define CP_WAIT(n)  asm volatile("cp.async.wait_group %0;" :: "n"(n) : "memory")

__device__ __forceinline__ void ldsm4(uint32_t* r, uint32_t addr) {
    asm volatile("ldmatrix.sync.aligned.m8n8.x4.shared.b16 {%0,%1,%2,%3}, [%4];"
                 : "=r"(r[0]), "=r"(r[1]), "=r"(r[2]), "=r"(r[3]) : "r"(addr));
}
__device__ __forceinline__ void hmma(float* c, const uint32_t* a, const uint32_t* b) {
    asm volatile(
        "mma.sync.aligned.m16n8k16.row.col.f32.bf16.bf16.f32 "
        "{%0,%1,%2,%3}, {%4,%5,%6,%7}, {%8,%9}, {%0,%1,%2,%3};"
        : "+f"(c[0]), "+f"(c[1]), "+f"(c[2]), "+f"(c[3])
        : "r"(a[0]), "r"(a[1]), "r"(a[2]), "r"(a[3]), "r"(b[0]), "r"(b[1]));
}

// ============================================================================
// prep kernels: fp32 -> bf16 hi/lo split
// ============================================================================
__global__ void prep_a(const float* __restrict__ content,
                       const float* __restrict__ motion,
                       __nv_bfloat16* __restrict__ hi,
                       __nv_bfloat16* __restrict__ lo)
{
    int idx = blockIdx.x * 256 + threadIdx.x;
    if (idx >= 32768 * 384) return;
    int m = idx / 384, k = idx - m * 384;
    float v = (k < 256) ? content[(m >> 9) * 256 + k]
                        : motion[(size_t)m * 128 + (k - 256)];
    __nv_bfloat16 h = __float2bfloat16(v);
    hi[idx] = h;
    lo[idx] = __float2bfloat16(v - __bfloat162float(h));
}

__global__ void prep_w(const float* __restrict__ W,
                       __nv_bfloat16* __restrict__ hi,
                       __nv_bfloat16* __restrict__ lo, int N, int K)
{
    int idx = blockIdx.x * 256 + threadIdx.x;
    if (idx >= N * K) return;
    int n = idx / K, k = idx - n * K;
    float v = W[(size_t)k * N + n];
    __nv_bfloat16 h = __float2bfloat16(v);
    hi[idx] = h;
    lo[idx] = __float2bfloat16(v - __bfloat162float(h));
}

// ============================================================================
// bf16x3 GEMM. CTA tile 128x128. BK=32 chunks; each chunk stages
// {Ahi, Alo, Bhi, Blo} once and runs all 3 passes on it.
// 8 warps: grid 2(M)x4(N), warp tile 64x32. fragments via ldmatrix.x4.
// SMEM rows padded to 40 bf16 (80B): 16B-aligned cp.async + conflict-free LDSM.
// ============================================================================
#define PADK 40
#define TILE_E (128 * PADK)          // elems per tile buffer
#define TILE_B (TILE_E * 2)          // bytes per tile buffer

template<int K, int NTOT, bool LEAKY, bool WRITE_F32>
__global__ __launch_bounds__(256, 2)
void gemm_hmma(const __nv_bfloat16* __restrict__ Ahi,
               const __nv_bfloat16* __restrict__ Alo,
               const __nv_bfloat16* __restrict__ Bhi,
               const __nv_bfloat16* __restrict__ Blo,
               const float* __restrict__ bias,
               float* __restrict__ Cout,
               __nv_bfloat16* __restrict__ NxtHi,
               __nv_bfloat16* __restrict__ NxtLo)
{
    constexpr int KC = K / 32;

    extern __shared__ __nv_bfloat16 smem[];
    const uint32_t smem_base = smem_u32(smem);

    const int tid  = threadIdx.x;
    const int lane = tid & 31;
    const int wid  = tid >> 5;
    const int g    = lane >> 2;        // 0..7
    const int t2   = (lane & 3) * 2;
    const int wm   = (wid >> 2) * 64;  // warp M offset
    const int wn   = (wid & 3) * 32;   // warp N offset

    const int rowBlock = blockIdx.y * 128;
    const int colBlock = blockIdx.x * 128;

    float acc[4][4][4];
    #pragma unroll
    for (int i = 0; i < 4; i++)
        #pragma unroll
        for (int j = 0; j < 4; j++)
            #pragma unroll
            for (int r = 0; r < 4; r++) acc[i][j][r] = 0.0f;

    // ldmatrix per-thread source rows/cols (see fragment mapping):
    // A x4: matrices {r0..7,k0..7},{r8..15,k0..7},{r0..7,k8..15},{r8..15,k8..15}
    const int aRowT = ((lane >> 3) & 1) * 8 + (lane & 7);  // + mt*16
    const int aColT = (lane >> 4) * 8;                     // + kb
    // B x4: matrices {n0..7,k0..7},{n0..7,k8..15},{n8..15,k0..7},{n8..15,k8..15}
    const int bRowT = ((lane >> 4) & 1) * 8 + (lane & 7);  // + ntpair*16
    const int bColT = ((lane >> 3) & 1) * 8;               // + kb

    // loader: 2048 16B chunks per K-chunk (4 tiles x 512), 8 per thread
    auto issue_chunk = [&](int c) {
        const int k0  = c * 32;
        const uint32_t dbase = smem_base + (uint32_t)(c & 1) * 4 * TILE_B;
        const int row = tid >> 2;          // 0..63
        const int ch  = tid & 3;           // 0..3
        #pragma unroll
        for (int i = 0; i < 8; ++i) {
            const int tile = i >> 1;             // 0:Ahi 1:Alo 2:Bhi 3:Blo
            const int r    = row + (i & 1) * 64; // 0..127
            const __nv_bfloat16* src;
            if (tile == 0)      src = Ahi + (size_t)(rowBlock + r) * K + k0 + ch * 8;
            else if (tile == 1) src = Alo + (size_t)(rowBlock + r) * K + k0 + ch * 8;
            else if (tile == 2) src = Bhi + (size_t)(colBlock + r) * K + k0 + ch * 8;
            else                src = Blo + (size_t)(colBlock + r) * K + k0 + ch * 8;
            cp16(dbase + (uint32_t)tile * TILE_B + (uint32_t)(r * PADK + ch * 8) * 2,
                 src);
        }
        CP_COMMIT();
    };

    issue_chunk(0);

    for (int c = 0; c < KC; ++c) {
        if (c + 1 < KC) { issue_chunk(c + 1); CP_WAIT(1); }
        else           { CP_WAIT(0); }
        __syncthreads();

        const uint32_t sb  = smem_base + (uint32_t)(c & 1) * 4 * TILE_B;
        const uint32_t sAhi = sb;
        const uint32_t sAlo = sb + TILE_B;
        const uint32_t sBhi = sb + 2 * TILE_B;
        const uint32_t sBlo = sb + 3 * TILE_B;

        #pragma unroll
        for (int ks = 0; ks < 2; ++ks) {
            const int kb = ks * 16;
            uint32_t a[4][4], b[4][2], bl[4][2];

            // Ahi fragments
            #pragma unroll
            for (int mt = 0; mt < 4; ++mt)
                ldsm4(a[mt], sAhi +
                      (uint32_t)((wm + mt * 16 + aRowT) * PADK + kb + aColT) * 2);
            // Bhi fragments (x4 covers two nt tiles)
            #pragma unroll
            for (int np = 0; np < 2; ++np) {
                uint32_t r4[4];
                ldsm4(r4, sBhi +
                      (uint32_t)((wn + np * 16 + bRowT) * PADK + kb + bColT) * 2);
                b[np * 2][0] = r4[0]; b[np * 2][1] = r4[1];
                b[np * 2 + 1][0] = r4[2]; b[np * 2 + 1][1] = r4[3];
            }
            // pass hh
            #pragma unroll
            for (int mt = 0; mt < 4; ++mt)
                #pragma unroll
                for (int nt = 0; nt < 4; ++nt)
                    hmma(acc[mt][nt], a[mt], b[nt]);

            // Blo fragments, pass hl (Ahi*Blo)
            #pragma unroll
            for (int np = 0; np < 2; ++np) {
                uint32_t r4[4];
                ldsm4(r4, sBlo +
                      (uint32_t)((wn + np * 16 + bRowT) * PADK + kb + bColT) * 2);
                bl[np * 2][0] = r4[0]; bl[np * 2][1] = r4[1];
                bl[np * 2 + 1][0] = r4[2]; bl[np * 2 + 1][1] = r4[3];
            }
            #pragma unroll
            for (int mt = 0; mt < 4; ++mt)
                #pragma unroll
                for (int nt = 0; nt < 4; ++nt)
                    hmma(acc[mt][nt], a[mt], bl[nt]);

            // Alo fragments (reuse a[]), pass lh (Alo*Bhi)
            #pragma unroll
            for (int mt = 0; mt < 4; ++mt)
                ldsm4(a[mt], sAlo +
                      (uint32_t)((wm + mt * 16 + aRowT) * PADK + kb + aColT) * 2);
            #pragma unroll
            for (int mt = 0; mt < 4; ++mt)
                #pragma unroll
                for (int nt = 0; nt < 4; ++nt)
                    hmma(acc[mt][nt], a[mt], b[nt]);
        }
        __syncthreads();
    }

    // ---- epilogue: bias (+leaky) -> fp32 out, or bf16 hi/lo for next layer ----
    #pragma unroll
    for (int mt = 0; mt < 4; ++mt) {
        #pragma unroll
        for (int half = 0; half < 2; ++half) {
            const int grow = rowBlock + wm + mt * 16 + g + half * 8;
            #pragma unroll
            for (int nt = 0; nt < 4; ++nt) {
                const int gcol = colBlock + wn + nt * 8 + t2;
                float v0 = acc[mt][nt][half * 2 + 0] + bias[gcol];
                float v1 = acc[mt][nt][half * 2 + 1] + bias[gcol + 1];
                if (LEAKY) {
                    v0 = v0 >= 0.f ? v0 : 0.2f * v0;
                    v1 = v1 >= 0.f ? v1 : 0.2f * v1;
                }
                const size_t base = (size_t)grow * NTOT + gcol;
                if (WRITE_F32) {
                    float2 o; o.x = v0; o.y = v1;
                    *reinterpret_cast<float2*>(&Cout[base]) = o;
                } else {
                    __nv_bfloat16 h0 = __float2bfloat16(v0);
                    __nv_bfloat16 h1 = __float2bfloat16(v1);
                    __nv_bfloat16 l0 = __float2bfloat16(v0 - __bfloat162float(h0));
                    __nv_bfloat16 l1 = __float2bfloat16(v1 - __bfloat162float(h1));
                    *reinterpret_cast<__nv_bfloat162*>(&NxtHi[base]) =
                        __halves2bfloat162(h0, h1);
                    *reinterpret_cast<__nv_bfloat162*>(&NxtLo[base]) =
                        __halves2bfloat162(l0, l1);
                }
            }
        }
    }
}

// ============================================================================
// launcher
// ============================================================================
extern "C" void kernel_launch(void* const* d_in, const int* in_sizes, int n_in,
                              void* d_out, int out_size)
{
    (void)in_sizes; (void)n_in; (void)out_size;
    const float* content = (const float*)d_in[0];
    const float* motion  = (const float*)d_in[1];
    const float* W1 = (const float*)d_in[2];
    const float* b1 = (const float*)d_in[3];
    const float* W2 = (const float*)d_in[4];
    const float* b2 = (const float*)d_in[5];
    const float* W3 = (const float*)d_in[6];
    const float* b3 = (const float*)d_in[7];
    float* out = (float*)d_out;

    __nv_bfloat16 *a1hi, *a1lo, *h1hi, *h1lo, *h2hi, *h2lo;
    __nv_bfloat16 *w1hi, *w1lo, *w2hi, *w2lo, *w3hi, *w3lo;
    cudaGetSymbolAddress((void**)&a1hi, g_a1hi);
    cudaGetSymbolAddress((void**)&a1lo, g_a1lo);
    cudaGetSymbolAddress((void**)&h1hi, g_h1hi);
    cudaGetSymbolAddress((void**)&h1lo, g_h1lo);
    cudaGetSymbolAddress((void**)&h2hi, g_h2hi);
    cudaGetSymbolAddress((void**)&h2lo, g_h2lo);
    cudaGetSymbolAddress((void**)&w1hi, g_w1hi);
    cudaGetSymbolAddress((void**)&w1lo, g_w1lo);
    cudaGetSymbolAddress((void**)&w2hi, g_w2hi);
    cudaGetSymbolAddress((void**)&w2lo, g_w2lo);
    cudaGetSymbolAddress((void**)&w3hi, g_w3hi);
    cudaGetSymbolAddress((void**)&w3lo, g_w3lo);

    const int SMEM = 2 * 4 * TILE_B;  // 81920 B
    cudaFuncSetAttribute((const void*)gemm_hmma<384, 256, true, false>,
                         cudaFuncAttributeMaxDynamicSharedMemorySize, SMEM);
    cudaFuncSetAttribute((const void*)gemm_hmma<256, 512, true, false>,
                         cudaFuncAttributeMaxDynamicSharedMemorySize, SMEM);
    cudaFuncSetAttribute((const void*)gemm_hmma<512, 1152, false, true>,
                         cudaFuncAttributeMaxDynamicSharedMemorySize, SMEM);

    // ---- prep: split inputs/weights into bf16 hi/lo ----
    prep_a<<<(32768 * 384 + 255) / 256, 256>>>(content, motion, a1hi, a1lo);
    prep_w<<<(256 * 384 + 255) / 256, 256>>>(W1, w1hi, w1lo, 256, 384);
    prep_w<<<(512 * 256 + 255) / 256, 256>>>(W2, w2hi, w2lo, 512, 256);
    prep_w<<<(1152 * 512 + 255) / 256, 256>>>(W3, w3hi, w3lo, 1152, 512);

    // ---- GEMM chain ----
    gemm_hmma<384, 256, true, false><<<dim3(2, 256), 256, SMEM>>>(
        a1hi, a1lo, w1hi, w1lo, b1, nullptr, h1hi, h1lo);
    gemm_hmma<256, 512, true, false><<<dim3(4, 256), 256, SMEM>>>(
        h1hi, h1lo, w2hi, w2lo, b2, nullptr, h2hi, h2lo);
    gemm_hmma<512, 1152, false, true><<<dim3(9, 256), 256, SMEM>>>(
        h2hi, h2lo, w3hi, w3lo, b3, out, nullptr, nullptr);
}

// round 5
// speedup vs baseline: 1.2873x; 1.2873x over previous
#include <cuda_runtime.h>
#include <cuda_bf16.h>
#include <cstdint>

// ============================================================================
// Problem: content[64,256], motion[64,512,128] -> M=32768 tokens
//   L1: [M,384]x[384,256]+b1, leaky(0.2)
//   L2: [M,256]x[256,512]+b2, leaky(0.2)
//   L3: [M,512]x[512,1152]+b3 -> out fp32
// Strategy: bf16x3 emulated-fp32 GEMM on mma.sync.m16n8k16.
//   C = Ahi*Bhi + Alo*Bhi + Ahi*Blo (A2B2 dropped, ~4e-6 rel).
// R5 = R3 structure (3-pass chunk stream, 2 tiles/chunk) + ldmatrix.x4 +
//      3-stage cp.async pipeline + single __syncthreads per chunk.
// ============================================================================

__device__ __nv_bfloat16 g_a1hi[12582912];   // [32768,384]
__device__ __nv_bfloat16 g_a1lo[12582912];
__device__ __nv_bfloat16 g_h1hi[8388608];    // [32768,256]
__device__ __nv_bfloat16 g_h1lo[8388608];
__device__ __nv_bfloat16 g_h2hi[16777216];   // [32768,512]
__device__ __nv_bfloat16 g_h2lo[16777216];
__device__ __nv_bfloat16 g_w1hi[98304],  g_w1lo[98304];    // [256,384]  (N,K)
__device__ __nv_bfloat16 g_w2hi[131072], g_w2lo[131072];   // [512,256]
__device__ __nv_bfloat16 g_w3hi[589824], g_w3lo[589824];   // [1152,512]

// ---- helpers ----
__device__ __forceinline__ uint32_t smem_u32(const void* p) {
    uint32_t a;
    asm("{ .reg .u64 t; cvta.to.shared.u64 t, %1; cvt.u32.u64 %0, t; }"
        : "=r"(a) : "l"(p));
    return a;
}
__device__ __forceinline__ void cp16(uint32_t dst, const void* src) {
    asm volatile("cp.async.cg.shared.global [%0], [%1], 16;"
                 :: "r"(dst), "l"(src) : "memory");
}
#define CP_COMMIT() asm volatile("cp.async.commit_group;" ::: "memory")
#define CP_WAIT(n)  asm volatile("cp.async.wait_group %0;" :: "n"(n) : "memory")

__device__ __forceinline__ void ldsm4(uint32_t* r, uint32_t addr) {
    asm volatile("ldmatrix.sync.aligned.m8n8.x4.shared.b16 {%0,%1,%2,%3}, [%4];"
                 : "=r"(r[0]), "=r"(r[1]), "=r"(r[2]), "=r"(r[3]) : "r"(addr));
}
__device__ __forceinline__ void hmma(float* c, const uint32_t* a, const uint32_t* b) {
    asm volatile(
        "mma.sync.aligned.m16n8k16.row.col.f32.bf16.bf16.f32 "
        "{%0,%1,%2,%3}, {%4,%5,%6,%7}, {%8,%9}, {%0,%1,%2,%3};"
        : "+f"(c[0]), "+f"(c[1]), "+f"(c[2]), "+f"(c[3])
        : "r"(a[0]), "r"(a[1]), "r"(a[2]), "r"(a[3]), "r"(b[0]), "r"(b[1]));
}

// ============================================================================
// prep kernels: fp32 -> bf16 hi/lo split
// ============================================================================
__global__ void prep_a(const float* __restrict__ content,
                       const float* __restrict__ motion,
                       __nv_bfloat16* __restrict__ hi,
                       __nv_bfloat16* __restrict__ lo)
{
    int idx = blockIdx.x * 256 + threadIdx.x;
    if (idx >= 32768 * 384) return;
    int m = idx / 384, k = idx - m * 384;
    float v = (k < 256) ? content[(m >> 9) * 256 + k]
                        : motion[(size_t)m * 128 + (k - 256)];
    __nv_bfloat16 h = __float2bfloat16(v);
    hi[idx] = h;
    lo[idx] = __float2bfloat16(v - __bfloat162float(h));
}

__global__ void prep_w(const float* __restrict__ W,
                       __nv_bfloat16* __restrict__ hi,
                       __nv_bfloat16* __restrict__ lo, int N, int K)
{
    int idx = blockIdx.x * 256 + threadIdx.x;
    if (idx >= N * K) return;
    int n = idx / K, k = idx - n * K;
    float v = W[(size_t)k * N + n];
    __nv_bfloat16 h = __float2bfloat16(v);
    hi[idx] = h;
    lo[idx] = __float2bfloat16(v - __bfloat162float(h));
}

// ============================================================================
// bf16x3 GEMM. CTA tile 128x128. BK=32; chunk stream c=0..3*K/32-1 where
//   pass = c/(K/32): 0 -> Ahi*Bhi, 1 -> Alo*Bhi, 2 -> Ahi*Blo.
// 8 warps: grid 2(M)x4(N), warp tile 64x32. Fragments via ldmatrix.x4.
// Rows padded to 40 bf16 (80B): 16B-aligned cp.async + conflict-free LDSM.
// 3-stage pipeline, one __syncthreads per chunk.
// ============================================================================
#define PADK 40
#define TILE_E (128 * PADK)
#define TILE_B (TILE_E * 2)          // 10240 B per tile
#define STG    3                     // pipeline stages
#define STG_B  (2 * TILE_B)          // As+Bs per stage

template<int K, int NTOT, bool LEAKY, bool WRITE_F32>
__global__ __launch_bounds__(256, 2)
void gemm_hmma(const __nv_bfloat16* __restrict__ Ahi,
               const __nv_bfloat16* __restrict__ Alo,
               const __nv_bfloat16* __restrict__ Bhi,
               const __nv_bfloat16* __restrict__ Blo,
               const float* __restrict__ bias,
               float* __restrict__ Cout,
               __nv_bfloat16* __restrict__ NxtHi,
               __nv_bfloat16* __restrict__ NxtLo)
{
    constexpr int KC = K / 32;
    constexpr int NC = 3 * KC;

    extern __shared__ __nv_bfloat16 smem[];
    const uint32_t smem_base = smem_u32(smem);

    const int tid  = threadIdx.x;
    const int lane = tid & 31;
    const int wid  = tid >> 5;
    const int g    = lane >> 2;
    const int t2   = (lane & 3) * 2;
    const int wm   = (wid >> 2) * 64;
    const int wn   = (wid & 3) * 32;

    const int rowBlock = blockIdx.y * 128;
    const int colBlock = blockIdx.x * 128;

    float acc[4][4][4];
    #pragma unroll
    for (int i = 0; i < 4; i++)
        #pragma unroll
        for (int j = 0; j < 4; j++)
            #pragma unroll
            for (int r = 0; r < 4; r++) acc[i][j][r] = 0.0f;

    // ldmatrix per-thread addresses (layouts verified in R4):
    // A x4 -> frags a0..a3 = {m0-7,k0-7},{m8-15,k0-7},{m0-7,k8-15},{m8-15,k8-15}
    const int aRowT = ((lane >> 3) & 1) * 8 + (lane & 7);
    const int aColT = (lane >> 4) * 8;
    // B x4 -> r0..r3 = {n0-7,k0-7},{n0-7,k8-15},{n8-15,k0-7},{n8-15,k8-15}
    const int bRowT = ((lane >> 4) & 1) * 8 + (lane & 7);
    const int bColT = ((lane >> 3) & 1) * 8;

    // loader: 1024 16B chunks per chunk (A 512 + B 512), 4 per thread
    const int ldRow = tid >> 2;   // 0..63
    const int ldCh  = tid & 3;    // 0..3
    auto issue_chunk = [&](int c) {
        const int pass = c / KC;
        const int kk   = c - pass * KC;
        const __nv_bfloat16* Aop = (pass == 1) ? Alo : Ahi;
        const __nv_bfloat16* Bop = (pass == 2) ? Blo : Bhi;
        const int k0  = kk * 32;
        const uint32_t sA = smem_base + (uint32_t)(c % STG) * STG_B;
        const uint32_t sB = sA + TILE_B;
        #pragma unroll
        for (int i = 0; i < 2; ++i) {
            const int r = ldRow + i * 64;
            const uint32_t off = (uint32_t)(r * PADK + ldCh * 8) * 2;
            cp16(sA + off, Aop + (size_t)(rowBlock + r) * K + k0 + ldCh * 8);
            cp16(sB + off, Bop + (size_t)(colBlock + r) * K + k0 + ldCh * 8);
        }
        CP_COMMIT();
    };

    issue_chunk(0);
    issue_chunk(1);

    for (int c = 0; c < NC; ++c) {
        CP_WAIT(STG - 2);       // chunk c resident (for this thread)
        __syncthreads();        // visible to all; prior compute of c-1 done
        if (c + STG - 1 < NC) issue_chunk(c + STG - 1);  // overwrites buf of c-1

        const uint32_t sA = smem_base + (uint32_t)(c % STG) * STG_B;
        const uint32_t sB = sA + TILE_B;

        #pragma unroll
        for (int ks = 0; ks < 2; ++ks) {
            const int kb = ks * 16;
            uint32_t a[4][4], b[4][2];
            #pragma unroll
            for (int mt = 0; mt < 4; ++mt)
                ldsm4(a[mt], sA +
                      (uint32_t)((wm + mt * 16 + aRowT) * PADK + kb + aColT) * 2);
            #pragma unroll
            for (int np = 0; np < 2; ++np) {
                uint32_t r4[4];
                ldsm4(r4, sB +
                      (uint32_t)((wn + np * 16 + bRowT) * PADK + kb + bColT) * 2);
                b[np * 2][0]     = r4[0]; b[np * 2][1]     = r4[1];
                b[np * 2 + 1][0] = r4[2]; b[np * 2 + 1][1] = r4[3];
            }
            #pragma unroll
            for (int mt = 0; mt < 4; ++mt)
                #pragma unroll
                for (int nt = 0; nt < 4; ++nt)
                    hmma(acc[mt][nt], a[mt], b[nt]);
        }
    }

    __syncthreads();

    // ---- epilogue: bias (+leaky) -> fp32 out, or bf16 hi/lo for next layer ----
    #pragma unroll
    for (int mt = 0; mt < 4; ++mt) {
        #pragma unroll
        for (int half = 0; half < 2; ++half) {
            const int grow = rowBlock + wm + mt * 16 + g + half * 8;
            #pragma unroll
            for (int nt = 0; nt < 4; ++nt) {
                const int gcol = colBlock + wn + nt * 8 + t2;
                float v0 = acc[mt][nt][half * 2 + 0] + bias[gcol];
                float v1 = acc[mt][nt][half * 2 + 1] + bias[gcol + 1];
                if (LEAKY) {
                    v0 = v0 >= 0.f ? v0 : 0.2f * v0;
                    v1 = v1 >= 0.f ? v1 : 0.2f * v1;
                }
                const size_t base = (size_t)grow * NTOT + gcol;
                if (WRITE_F32) {
                    float2 o; o.x = v0; o.y = v1;
                    *reinterpret_cast<float2*>(&Cout[base]) = o;
                } else {
                    __nv_bfloat16 h0 = __float2bfloat16(v0);
                    __nv_bfloat16 h1 = __float2bfloat16(v1);
                    __nv_bfloat16 l0 = __float2bfloat16(v0 - __bfloat162float(h0));
                    __nv_bfloat16 l1 = __float2bfloat16(v1 - __bfloat162float(h1));
                    *reinterpret_cast<__nv_bfloat162*>(&NxtHi[base]) =
                        __halves2bfloat162(h0, h1);
                    *reinterpret_cast<__nv_bfloat162*>(&NxtLo[base]) =
                        __halves2bfloat162(l0, l1);
                }
            }
        }
    }
}

// ============================================================================
// launcher
// ============================================================================
extern "C" void kernel_launch(void* const* d_in, const int* in_sizes, int n_in,
                              void* d_out, int out_size)
{
    (void)in_sizes; (void)n_in; (void)out_size;
    const float* content = (const float*)d_in[0];
    const float* motion  = (const float*)d_in[1];
    const float* W1 = (const float*)d_in[2];
    const float* b1 = (const float*)d_in[3];
    const float* W2 = (const float*)d_in[4];
    const float* b2 = (const float*)d_in[5];
    const float* W3 = (const float*)d_in[6];
    const float* b3 = (const float*)d_in[7];
    float* out = (float*)d_out;

    __nv_bfloat16 *a1hi, *a1lo, *h1hi, *h1lo, *h2hi, *h2lo;
    __nv_bfloat16 *w1hi, *w1lo, *w2hi, *w2lo, *w3hi, *w3lo;
    cudaGetSymbolAddress((void**)&a1hi, g_a1hi);
    cudaGetSymbolAddress((void**)&a1lo, g_a1lo);
    cudaGetSymbolAddress((void**)&h1hi, g_h1hi);
    cudaGetSymbolAddress((void**)&h1lo, g_h1lo);
    cudaGetSymbolAddress((void**)&h2hi, g_h2hi);
    cudaGetSymbolAddress((void**)&h2lo, g_h2lo);
    cudaGetSymbolAddress((void**)&w1hi, g_w1hi);
    cudaGetSymbolAddress((void**)&w1lo, g_w1lo);
    cudaGetSymbolAddress((void**)&w2hi, g_w2hi);
    cudaGetSymbolAddress((void**)&w2lo, g_w2lo);
    cudaGetSymbolAddress((void**)&w3hi, g_w3hi);
    cudaGetSymbolAddress((void**)&w3lo, g_w3lo);

    const int SMEM = STG * STG_B;  // 61440 B
    cudaFuncSetAttribute((const void*)gemm_hmma<384, 256, true, false>,
                         cudaFuncAttributeMaxDynamicSharedMemorySize, SMEM);
    cudaFuncSetAttribute((const void*)gemm_hmma<256, 512, true, false>,
                         cudaFuncAttributeMaxDynamicSharedMemorySize, SMEM);
    cudaFuncSetAttribute((const void*)gemm_hmma<512, 1152, false, true>,
                         cudaFuncAttributeMaxDynamicSharedMemorySize, SMEM);

    // ---- prep: split inputs/weights into bf16 hi/lo ----
    prep_a<<<(32768 * 384 + 255) / 256, 256>>>(content, motion, a1hi, a1lo);
    prep_w<<<(256 * 384 + 255) / 256, 256>>>(W1, w1hi, w1lo, 256, 384);
    prep_w<<<(512 * 256 + 255) / 256, 256>>>(W2, w2hi, w2lo, 512, 256);
    prep_w<<<(1152 * 512 + 255) / 256, 256>>>(W3, w3hi, w3lo, 1152, 512);

    // ---- GEMM chain ----
    gemm_hmma<384, 256, true, false><<<dim3(2, 256), 256, SMEM>>>(
        a1hi, a1lo, w1hi, w1lo, b1, nullptr, h1hi, h1lo);
    gemm_hmma<256, 512, true, false><<<dim3(4, 256), 256, SMEM>>>(
        h1hi, h1lo, w2hi, w2lo, b2, nullptr, h2hi, h2lo);
    gemm_hmma<512, 1152, false, true><<<dim3(9, 256), 256, SMEM>>>(
        h2hi, h2lo, w3hi, w3lo, b3, out, nullptr, nullptr);
}

// round 6
// speedup vs baseline: 1.5443x; 1.1996x over previous
#include <cuda_runtime.h>
#include <cuda_bf16.h>
#include <cstdint>

// ============================================================================
// Problem: content[64,256], motion[64,512,128] -> M=32768 tokens
//   L1: [M,384]x[384,256]+b1, leaky(0.2)
//   L2: [M,256]x[256,512]+b2, leaky(0.2)
//   L3: [M,512]x[512,1152]+b3 -> out fp32
// Strategy: bf16x3 emulated-fp32 GEMM on mma.sync.m16n8k16.
//   C = Ahi*Bhi + Alo*Bhi + Ahi*Blo (A2B2 dropped, ~4e-6 rel).
// R6: coalesced hi/lo K-chunks (stage {Ahi,Alo,Bhi,Blo} once, run all 3
//     passes) with REGISTER-SAFE fragment reuse (a16+b8 only, reload instead
//     of triple-buffer), single __syncthreads per chunk, 2-stage pipeline.
// ============================================================================

__device__ __nv_bfloat16 g_a1hi[12582912];   // [32768,384]
__device__ __nv_bfloat16 g_a1lo[12582912];
__device__ __nv_bfloat16 g_h1hi[8388608];    // [32768,256]
__device__ __nv_bfloat16 g_h1lo[8388608];
__device__ __nv_bfloat16 g_h2hi[16777216];   // [32768,512]
__device__ __nv_bfloat16 g_h2lo[16777216];
__device__ __nv_bfloat16 g_w1hi[98304],  g_w1lo[98304];    // [256,384]  (N,K)
__device__ __nv_bfloat16 g_w2hi[131072], g_w2lo[131072];   // [512,256]
__device__ __nv_bfloat16 g_w3hi[589824], g_w3lo[589824];   // [1152,512]

// ---- helpers ----
__device__ __forceinline__ uint32_t smem_u32(const void* p) {
    uint32_t a;
    asm("{ .reg .u64 t; cvta.to.shared.u64 t, %1; cvt.u32.u64 %0, t; }"
        : "=r"(a) : "l"(p));
    return a;
}
__device__ __forceinline__ void cp16(uint32_t dst, const void* src) {
    asm volatile("cp.async.cg.shared.global [%0], [%1], 16;"
                 :: "r"(dst), "l"(src) : "memory");
}
#define CP_COMMIT() asm volatile("cp.async.commit_group;" ::: "memory")
#define CP_WAIT(n)  asm volatile("cp.async.wait_group %0;" :: "n"(n) : "memory")

__device__ __forceinline__ void ldsm4(uint32_t* r, uint32_t addr) {
    asm volatile("ldmatrix.sync.aligned.m8n8.x4.shared.b16 {%0,%1,%2,%3}, [%4];"
                 : "=r"(r[0]), "=r"(r[1]), "=r"(r[2]), "=r"(r[3]) : "r"(addr));
}
__device__ __forceinline__ void hmma(float* c, const uint32_t* a, const uint32_t* b) {
    asm volatile(
        "mma.sync.aligned.m16n8k16.row.col.f32.bf16.bf16.f32 "
        "{%0,%1,%2,%3}, {%4,%5,%6,%7}, {%8,%9}, {%0,%1,%2,%3};"
        : "+f"(c[0]), "+f"(c[1]), "+f"(c[2]), "+f"(c[3])
        : "r"(a[0]), "r"(a[1]), "r"(a[2]), "r"(a[3]), "r"(b[0]), "r"(b[1]));
}

// ============================================================================
// prep kernels: fp32 -> bf16 hi/lo split
// ============================================================================
__global__ void prep_a(const float* __restrict__ content,
                       const float* __restrict__ motion,
                       __nv_bfloat16* __restrict__ hi,
                       __nv_bfloat16* __restrict__ lo)
{
    int idx = blockIdx.x * 256 + threadIdx.x;
    if (idx >= 32768 * 384) return;
    int m = idx / 384, k = idx - m * 384;
    float v = (k < 256) ? content[(m >> 9) * 256 + k]
                        : motion[(size_t)m * 128 + (k - 256)];
    __nv_bfloat16 h = __float2bfloat16(v);
    hi[idx] = h;
    lo[idx] = __float2bfloat16(v - __bfloat162float(h));
}

__global__ void prep_w(const float* __restrict__ W,
                       __nv_bfloat16* __restrict__ hi,
                       __nv_bfloat16* __restrict__ lo, int N, int K)
{
    int idx = blockIdx.x * 256 + threadIdx.x;
    if (idx >= N * K) return;
    int n = idx / K, k = idx - n * K;
    float v = W[(size_t)k * N + n];
    __nv_bfloat16 h = __float2bfloat16(v);
    hi[idx] = h;
    lo[idx] = __float2bfloat16(v - __bfloat162float(h));
}

// ============================================================================
// bf16x3 GEMM. CTA tile 128x128, BK=32. Each K-chunk stages 4 tiles
// {Ahi, Alo, Bhi, Blo}; all 3 passes run against the staged chunk.
// 8 warps: grid 2(M)x4(N), warp tile 64x32. Fragments via ldmatrix.x4,
// capped at a[4][4]+b[4][2] (reload Bhi for the lh pass).
// Rows padded to 40 bf16 (80B): 16B-aligned cp.async + conflict-free LDSM.
// 2-stage pipeline, one __syncthreads per chunk.
// ============================================================================
#define PADK 40
#define TILE_E (128 * PADK)
#define TILE_B (TILE_E * 2)          // 10240 B per tile
#define STG_B  (4 * TILE_B)          // {Ahi,Alo,Bhi,Blo} per stage

template<int K, int NTOT, bool LEAKY, bool WRITE_F32>
__global__ __launch_bounds__(256, 2)
void gemm_hmma(const __nv_bfloat16* __restrict__ Ahi,
               const __nv_bfloat16* __restrict__ Alo,
               const __nv_bfloat16* __restrict__ Bhi,
               const __nv_bfloat16* __restrict__ Blo,
               const float* __restrict__ bias,
               float* __restrict__ Cout,
               __nv_bfloat16* __restrict__ NxtHi,
               __nv_bfloat16* __restrict__ NxtLo)
{
    constexpr int KC = K / 32;

    extern __shared__ __nv_bfloat16 smem[];
    const uint32_t smem_base = smem_u32(smem);

    const int tid  = threadIdx.x;
    const int lane = tid & 31;
    const int wid  = tid >> 5;
    const int g    = lane >> 2;
    const int t2   = (lane & 3) * 2;
    const int wm   = (wid >> 2) * 64;
    const int wn   = (wid & 3) * 32;

    const int rowBlock = blockIdx.y * 128;
    const int colBlock = blockIdx.x * 128;

    float acc[4][4][4];
    #pragma unroll
    for (int i = 0; i < 4; i++)
        #pragma unroll
        for (int j = 0; j < 4; j++)
            #pragma unroll
            for (int r = 0; r < 4; r++) acc[i][j][r] = 0.0f;

    // ldmatrix per-thread addresses (layouts verified in R4/R5):
    const int aRowT = ((lane >> 3) & 1) * 8 + (lane & 7);
    const int aColT = (lane >> 4) * 8;
    const int bRowT = ((lane >> 4) & 1) * 8 + (lane & 7);
    const int bColT = ((lane >> 3) & 1) * 8;

    // loader: 4 tiles x 512 16B-chunks = 2048 per K-chunk, 8 per thread
    const int ldRow = tid >> 2;   // 0..63
    const int ldCh  = tid & 3;    // 0..3
    auto issue_chunk = [&](int c) {
        const int k0 = c * 32;
        const uint32_t sb = smem_base + (uint32_t)(c & 1) * STG_B;
        #pragma unroll
        for (int i = 0; i < 2; ++i) {
            const int r = ldRow + i * 64;
            const uint32_t off = (uint32_t)(r * PADK + ldCh * 8) * 2;
            const size_t ga = (size_t)(rowBlock + r) * K + k0 + ldCh * 8;
            const size_t gb = (size_t)(colBlock + r) * K + k0 + ldCh * 8;
            cp16(sb + off,                Ahi + ga);
            cp16(sb + TILE_B + off,       Alo + ga);
            cp16(sb + 2 * TILE_B + off,   Bhi + gb);
            cp16(sb + 3 * TILE_B + off,   Blo + gb);
        }
        CP_COMMIT();
    };

    issue_chunk(0);

    for (int c = 0; c < KC; ++c) {
        CP_WAIT(0);            // chunk c landed (this thread's groups)
        __syncthreads();       // all threads: chunk c visible, compute c-1 done
        if (c + 1 < KC) issue_chunk(c + 1);  // overwrites buffer read at c-1

        const uint32_t sb   = smem_base + (uint32_t)(c & 1) * STG_B;
        const uint32_t sAhi = sb;
        const uint32_t sAlo = sb + TILE_B;
        const uint32_t sBhi = sb + 2 * TILE_B;
        const uint32_t sBlo = sb + 3 * TILE_B;

        #pragma unroll
        for (int ks = 0; ks < 2; ++ks) {
            const int kb = ks * 16;
            uint32_t a[4][4], b[4][2];
            const uint32_t aOff =
                (uint32_t)((wm + aRowT) * PADK + kb + aColT) * 2;
            const uint32_t bOff0 =
                (uint32_t)((wn + bRowT) * PADK + kb + bColT) * 2;
            const uint32_t bOff1 =
                (uint32_t)((wn + 16 + bRowT) * PADK + kb + bColT) * 2;

            // ---- pass hh: Ahi * Bhi ----
            #pragma unroll
            for (int mt = 0; mt < 4; ++mt)
                ldsm4(a[mt], sAhi + aOff + (uint32_t)(mt * 16 * PADK) * 2);
            {
                uint32_t r4[4];
                ldsm4(r4, sBhi + bOff0);
                b[0][0] = r4[0]; b[0][1] = r4[1];
                b[1][0] = r4[2]; b[1][1] = r4[3];
                ldsm4(r4, sBhi + bOff1);
                b[2][0] = r4[0]; b[2][1] = r4[1];
                b[3][0] = r4[2]; b[3][1] = r4[3];
            }
            #pragma unroll
            for (int mt = 0; mt < 4; ++mt)
                #pragma unroll
                for (int nt = 0; nt < 4; ++nt)
                    hmma(acc[mt][nt], a[mt], b[nt]);

            // ---- pass hl: Ahi * Blo (a still holds Ahi) ----
            {
                uint32_t r4[4];
                ldsm4(r4, sBlo + bOff0);
                b[0][0] = r4[0]; b[0][1] = r4[1];
                b[1][0] = r4[2]; b[1][1] = r4[3];
                ldsm4(r4, sBlo + bOff1);
                b[2][0] = r4[0]; b[2][1] = r4[1];
                b[3][0] = r4[2]; b[3][1] = r4[3];
            }
            #pragma unroll
            for (int mt = 0; mt < 4; ++mt)
                #pragma unroll
                for (int nt = 0; nt < 4; ++nt)
                    hmma(acc[mt][nt], a[mt], b[nt]);

            // ---- pass lh: Alo * Bhi (reload both) ----
            #pragma unroll
            for (int mt = 0; mt < 4; ++mt)
                ldsm4(a[mt], sAlo + aOff + (uint32_t)(mt * 16 * PADK) * 2);
            {
                uint32_t r4[4];
                ldsm4(r4, sBhi + bOff0);
                b[0][0] = r4[0]; b[0][1] = r4[1];
                b[1][0] = r4[2]; b[1][1] = r4[3];
                ldsm4(r4, sBhi + bOff1);
                b[2][0] = r4[0]; b[2][1] = r4[1];
                b[3][0] = r4[2]; b[3][1] = r4[3];
            }
            #pragma unroll
            for (int mt = 0; mt < 4; ++mt)
                #pragma unroll
                for (int nt = 0; nt < 4; ++nt)
                    hmma(acc[mt][nt], a[mt], b[nt]);
        }
    }

    __syncthreads();

    // ---- epilogue: bias (+leaky) -> fp32 out, or bf16 hi/lo for next layer ----
    #pragma unroll
    for (int mt = 0; mt < 4; ++mt) {
        #pragma unroll
        for (int half = 0; half < 2; ++half) {
            const int grow = rowBlock + wm + mt * 16 + g + half * 8;
            #pragma unroll
            for (int nt = 0; nt < 4; ++nt) {
                const int gcol = colBlock + wn + nt * 8 + t2;
                float v0 = acc[mt][nt][half * 2 + 0] + bias[gcol];
                float v1 = acc[mt][nt][half * 2 + 1] + bias[gcol + 1];
                if (LEAKY) {
                    v0 = v0 >= 0.f ? v0 : 0.2f * v0;
                    v1 = v1 >= 0.f ? v1 : 0.2f * v1;
                }
                const size_t base = (size_t)grow * NTOT + gcol;
                if (WRITE_F32) {
                    float2 o; o.x = v0; o.y = v1;
                    *reinterpret_cast<float2*>(&Cout[base]) = o;
                } else {
                    __nv_bfloat16 h0 = __float2bfloat16(v0);
                    __nv_bfloat16 h1 = __float2bfloat16(v1);
                    __nv_bfloat16 l0 = __float2bfloat16(v0 - __bfloat162float(h0));
                    __nv_bfloat16 l1 = __float2bfloat16(v1 - __bfloat162float(h1));
                    *reinterpret_cast<__nv_bfloat162*>(&NxtHi[base]) =
                        __halves2bfloat162(h0, h1);
                    *reinterpret_cast<__nv_bfloat162*>(&NxtLo[base]) =
                        __halves2bfloat162(l0, l1);
                }
            }
        }
    }
}

// ============================================================================
// launcher
// ============================================================================
extern "C" void kernel_launch(void* const* d_in, const int* in_sizes, int n_in,
                              void* d_out, int out_size)
{
    (void)in_sizes; (void)n_in; (void)out_size;
    const float* content = (const float*)d_in[0];
    const float* motion  = (const float*)d_in[1];
    const float* W1 = (const float*)d_in[2];
    const float* b1 = (const float*)d_in[3];
    const float* W2 = (const float*)d_in[4];
    const float* b2 = (const float*)d_in[5];
    const float* W3 = (const float*)d_in[6];
    const float* b3 = (const float*)d_in[7];
    float* out = (float*)d_out;

    __nv_bfloat16 *a1hi, *a1lo, *h1hi, *h1lo, *h2hi, *h2lo;
    __nv_bfloat16 *w1hi, *w1lo, *w2hi, *w2lo, *w3hi, *w3lo;
    cudaGetSymbolAddress((void**)&a1hi, g_a1hi);
    cudaGetSymbolAddress((void**)&a1lo, g_a1lo);
    cudaGetSymbolAddress((void**)&h1hi, g_h1hi);
    cudaGetSymbolAddress((void**)&h1lo, g_h1lo);
    cudaGetSymbolAddress((void**)&h2hi, g_h2hi);
    cudaGetSymbolAddress((void**)&h2lo, g_h2lo);
    cudaGetSymbolAddress((void**)&w1hi, g_w1hi);
    cudaGetSymbolAddress((void**)&w1lo, g_w1lo);
    cudaGetSymbolAddress((void**)&w2hi, g_w2hi);
    cudaGetSymbolAddress((void**)&w2lo, g_w2lo);
    cudaGetSymbolAddress((void**)&w3hi, g_w3hi);
    cudaGetSymbolAddress((void**)&w3lo, g_w3lo);

    const int SMEM = 2 * STG_B;  // 81920 B
    cudaFuncSetAttribute((const void*)gemm_hmma<384, 256, true, false>,
                         cudaFuncAttributeMaxDynamicSharedMemorySize, SMEM);
    cudaFuncSetAttribute((const void*)gemm_hmma<256, 512, true, false>,
                         cudaFuncAttributeMaxDynamicSharedMemorySize, SMEM);
    cudaFuncSetAttribute((const void*)gemm_hmma<512, 1152, false, true>,
                         cudaFuncAttributeMaxDynamicSharedMemorySize, SMEM);

    // ---- prep: split inputs/weights into bf16 hi/lo ----
    prep_a<<<(32768 * 384 + 255) / 256, 256>>>(content, motion, a1hi, a1lo);
    prep_w<<<(256 * 384 + 255) / 256, 256>>>(W1, w1hi, w1lo, 256, 384);
    prep_w<<<(512 * 256 + 255) / 256, 256>>>(W2, w2hi, w2lo, 512, 256);
    prep_w<<<(1152 * 512 + 255) / 256, 256>>>(W3, w3hi, w3lo, 1152, 512);

    // ---- GEMM chain ----
    gemm_hmma<384, 256, true, false><<<dim3(2, 256), 256, SMEM>>>(
        a1hi, a1lo, w1hi, w1lo, b1, nullptr, h1hi, h1lo);
    gemm_hmma<256, 512, true, false><<<dim3(4, 256), 256, SMEM>>>(
        h1hi, h1lo, w2hi, w2lo, b2, nullptr, h2hi, h2lo);
    gemm_hmma<512, 1152, false, true><<<dim3(9, 256), 256, SMEM>>>(
        h2hi, h2lo, w3hi, w3lo, b3, out, nullptr, nullptr);
}